// round 1
// baseline (speedup 1.0000x reference)
#include <cuda_runtime.h>
#include <math.h>

// ROI align (14x14 bilinear grid) + 2x2 maxpool -> (B,N,C,7,7)
// B=4, N=512, C=256, Hf=Wf=50, IMG=800 -> fx=fy=0.0625
// Proposal box: x,y in [0,22], w,h in [5,22] (feature units) -> patch fits 22x22.

#define BB 4
#define NN 512
#define CC 256
#define HF 50
#define WF 50
#define OUTD 14
#define POOL 7
#define TC 16            // channels per tile
#define PSTRIDE 23       // padded row stride for the patch (max h = 22, odd stride)
#define PMAXROWS 22

__global__ __launch_bounds__(256)
void roi_align_pool_kernel(const float* __restrict__ proposals,
                           const float* __restrict__ features,
                           float* __restrict__ out)
{
    const int bn = blockIdx.x;          // b*N + n
    const int b  = bn / NN;

    __shared__ int   s_rl[OUTD], s_rh[OUTD], s_cl[OUTD], s_ch[OUTD];
    __shared__ float s_rf[OUTD], s_cf[OUTD];
    __shared__ int   s_box[4];          // x, y, w, h
    __shared__ float patch[TC][PMAXROWS * PSTRIDE];

    const int tid = threadIdx.x;

    if (tid < 4) {
        // fx = Hf/IMG = 0.0625 exactly; trunc-cast matches astype(int32) for >=0
        s_box[tid] = (int)(proposals[bn * 4 + tid] * 0.0625f);
    }
    __syncthreads();

    if (tid < 2 * OUTD) {
        const int  i     = tid & 15 ? tid % OUTD : 0;   // (avoid div) -- see below
        // simpler & correct:
        const int  ii    = tid < OUTD ? tid : tid - OUTD;
        const bool isRow = tid < OUTD;
        const int  len   = isRow ? s_box[2] : s_box[3]; // rows use w, cols use h
        const float scale = (float)(len - 1) / 13.0f;   // f32 div, matches jnp
        const float c     = (float)ii * scale;
        const int   low   = (int)floorf(c);
        const float frac  = c - (float)low;
        const int   high  = min(low + 1, len - 1);
        (void)i;
        if (isRow) { s_rl[ii] = low; s_rh[ii] = high; s_rf[ii] = frac; }
        else       { s_cl[ii] = low; s_ch[ii] = high; s_cf[ii] = frac; }
    }
    __syncthreads();

    const int x = s_box[0], y = s_box[1], w = s_box[2], h = s_box[3];
    const int patch_elems = w * h;

    for (int c0 = 0; c0 < CC; c0 += TC) {
        // ---- stage TC channel patches into smem (coalesced along feature rows)
        const int total = TC * patch_elems;
        for (int idx = tid; idx < total; idx += 256) {
            const int tc  = idx / patch_elems;
            const int rem = idx - tc * patch_elems;
            const int r   = rem / h;
            const int col = rem - r * h;
            patch[tc][r * PSTRIDE + col] =
                features[(((b * CC) + c0 + tc) * HF + (x + r)) * WF + (y + col)];
        }
        __syncthreads();

        // ---- each work item = one pooled output (max over 2x2 bilinear points)
        for (int idx = tid; idx < TC * 49; idx += 256) {
            const int tc = idx / 49;
            const int p  = idx - tc * 49;
            const int pi = p / 7;
            const int pj = p - pi * 7;

            const float* __restrict__ pp = patch[tc];
            float m = -INFINITY;
            #pragma unroll
            for (int di = 0; di < 2; di++) {
                const int   i  = 2 * pi + di;
                const int   rl = s_rl[i], rh = s_rh[i];
                const float rf = s_rf[i];
                #pragma unroll
                for (int dj = 0; dj < 2; dj++) {
                    const int   j  = 2 * pj + dj;
                    const int   cl = s_cl[j], ch = s_ch[j];
                    const float cf = s_cf[j];
                    const float v00 = pp[rl * PSTRIDE + cl];
                    const float v01 = pp[rl * PSTRIDE + ch];
                    const float v10 = pp[rh * PSTRIDE + cl];
                    const float v11 = pp[rh * PSTRIDE + ch];
                    const float top = v00 * (1.0f - cf) + v01 * cf;
                    const float bot = v10 * (1.0f - cf) + v11 * cf;
                    const float v   = top * (1.0f - rf) + bot * rf;
                    m = fmaxf(m, v);
                }
            }
            out[(bn * CC + c0 + tc) * 49 + p] = m;
        }
        __syncthreads();
    }
}

extern "C" void kernel_launch(void* const* d_in, const int* in_sizes, int n_in,
                              void* d_out, int out_size)
{
    const float* proposals = (const float*)d_in[0];   // (B,N,4) f32
    const float* features  = (const float*)d_in[1];   // (B,C,Hf,Wf) f32
    float* out = (float*)d_out;                       // (B,N,C,7,7) f32
    (void)in_sizes; (void)n_in; (void)out_size;

    roi_align_pool_kernel<<<BB * NN, 256>>>(proposals, features, out);
}